// round 5
// baseline (speedup 1.0000x reference)
#include <cuda_runtime.h>

#define BSZ   32
#define NSZ   256
#define KSZ   16
#define INC   32
#define OUTC  32
#define XS    (NSZ*INC)
#define NBLK  128

// Scratch (allocation-free)
__device__ float4 g_S4[BSZ * 32 * 8];                 // [s][B][iq] (float4)
__device__ float4 g_wdT4[KSZ * OUTC * 8];             // [k][o][iq] (float4)
__device__ float  g_Tpart[8 * 2 * BSZ * KSZ * OUTC];  // [Bg][p][s][k][o]
__device__ unsigned int g_bar;                        // monotonic barrier counter

__device__ __forceinline__ void gridbar() {
    __threadfence();
    __syncthreads();
    if (threadIdx.x == 0) {
        unsigned int my = atomicAdd(&g_bar, 1u);
        unsigned int target = (my / NBLK + 1u) * NBLK;
        unsigned int v;
        do {
            asm volatile("ld.acquire.gpu.u32 %0, [%1];" : "=r"(v) : "l"(&g_bar));
        } while (v < target);
    }
    __syncthreads();
}

__global__ void __launch_bounds__(512, 1) fused_kernel(
    const float* __restrict__ x,
    const float* __restrict__ w_diag,
    const float* __restrict__ w_off,
    const float* __restrict__ b1,
    const int*   __restrict__ perm,
    float*       __restrict__ out)
{
    __shared__ float4 buf4[2304];   // phase1: W4[0,1152)+S4[1152,2304); phase2: wdsh4[0,1056)
    __shared__ float  tsh[256];
    __shared__ float  bsh[32];
    __shared__ int    permS[64];

    const int b = blockIdx.x;
    const int t = threadIdx.x;

    // ---- phase-2 constants, prefetched off the critical path ----
    const int s2 = b >> 2, kq = b & 3;
    if (t < 64)            permS[t]    = __ldg(&perm[kq * 64 + t]);
    else if (t < 96)       bsh[t - 64] = __ldg(&b1[t - 64]);

    // ---- phase-1 W prefetch (independent input, issue immediately) ----
    const int k1 = b >> 3, Bg = b & 7;
    float4 wreg[4];
    if (t < 256) {
        const float4* woff4 = (const float4*)w_off;   // [c][k][B/4]
#pragma unroll
        for (int j = 0; j < 4; j++) {
            int c = j * 256 + t;                       // c = o*32+i
            wreg[j] = __ldg(&woff4[c * 128 + k1 * 8 + Bg]);
        }
    }

    // ================= phase 0: S pooling + w_diag transpose =================
    if (b < 64) {
        int gid = b * 512 + t;                         // [s][B][i], i fastest
        int B = (gid >> 5) & 31, i = gid & 31;
        const float* xs = x + (gid >> 10) * XS + i;
        float acc = 0.f;
#pragma unroll
        for (int r = 0; r < 8; r++)
            acc += __ldg(&xs[__ldg(&perm[B * 8 + r]) * 32]);
        ((float*)g_S4)[gid] = acc;
    } else if (b < 96) {
        int e = (b - 64) * 512 + t;                    // e = k*1024 + c
        int k = e >> 10, c = e & 1023;
        ((float*)g_wdT4)[e] = __ldg(&w_diag[c * 16 + k]);
    }

    gridbar();

    // ================= phase 1: T partials, block = (k1, Bg) =================
    {
        float4* W4 = buf4;            // [(o*4+Bl)*9 + iq]
        float4* S4 = buf4 + 1152;     // [(s*4+Bl)*9 + iq]
        float*  Wf = (float*)W4;
        float*  stage = (float*)buf4;

        if (t < 256) {
#pragma unroll
            for (int j = 0; j < 4; j++) {              // S slice from g_S
                int e = j * 256 + t;                   // float4 index
                int s = e >> 5, Bl = (e >> 3) & 3, iq = e & 7;
                S4[(s * 4 + Bl) * 9 + iq] = g_S4[s * 256 + (Bg * 4 + Bl) * 8 + iq];
            }
#pragma unroll
            for (int j = 0; j < 4; j++) {              // W regs -> padded smem
                int c = j * 256 + t;
                int o = c >> 5, i = c & 31;
                Wf[(o * 4 + 0) * 36 + i] = wreg[j].x;
                Wf[(o * 4 + 1) * 36 + i] = wreg[j].y;
                Wf[(o * 4 + 2) * 36 + i] = wreg[j].z;
                Wf[(o * 4 + 3) * 36 + i] = wreg[j].w;
            }
        }
        __syncthreads();

        float acc[2][2][8];
        if (t < 256) {
            const int sp = t >> 4, og = (t >> 2) & 3, Bq = t & 3;
            const float4* Su0 = S4 + (sp * 4 + Bq) * 9;
            const float4* Su1 = S4 + ((sp + 16) * 4 + Bq) * 9;
            const float4* Sv0 = S4 + (sp * 4 + (Bq ^ 1)) * 9;
            const float4* Sv1 = S4 + ((sp + 16) * 4 + (Bq ^ 1)) * 9;
#pragma unroll
            for (int j = 0; j < 32; j++) ((float*)acc)[j] = 0.f;
#pragma unroll
            for (int iq = 0; iq < 8; iq++) {
                float4 u0 = Su0[iq], u1 = Su1[iq], v0 = Sv0[iq], v1 = Sv1[iq];
#pragma unroll
                for (int oo = 0; oo < 8; oo++) {
                    float4 w = W4[((og + 4 * oo) * 4 + Bq) * 9 + iq];
                    acc[0][0][oo] += w.x*u0.x + w.y*u0.y + w.z*u0.z + w.w*u0.w;
                    acc[0][1][oo] += w.x*v0.x + w.y*v0.y + w.z*v0.z + w.w*v0.w;
                    acc[1][0][oo] += w.x*u1.x + w.y*u1.y + w.z*u1.z + w.w*u1.w;
                    acc[1][1][oo] += w.x*v1.x + w.y*v1.y + w.z*v1.z + w.w*v1.w;
                }
            }
        }
        __syncthreads();
        if (t < 256) {
#pragma unroll
            for (int ss = 0; ss < 2; ss++)
#pragma unroll
                for (int p = 0; p < 2; p++)
#pragma unroll
                    for (int oo = 0; oo < 8; oo++)
                        stage[t * 33 + (ss * 16 + p * 8 + oo)] = acc[ss][p][oo];
        }
        __syncthreads();
        if (t < 256) {
            int sp2 = t >> 4, og2 = (t >> 2) & 3, jq = t & 3;
#pragma unroll
            for (int jj = 0; jj < 8; jj++) {
                int j = jq * 8 + jj;
                float v = 0.f;
#pragma unroll
                for (int q = 0; q < 4; q++)
                    v += stage[(sp2 * 16 + og2 * 4 + q) * 33 + j];
                int ss = j >> 4, p = (j >> 3) & 1, oo = j & 7;
                g_Tpart[(((Bg * 2 + p) * 32 + (sp2 + 16 * ss)) * 16 + k1) * 32
                        + (og2 + 4 * oo)] = v;
            }
        }
    }

    gridbar();

    // ================= phase 2: finalize, block = (s2, kq) =================
    float4* wdsh4 = buf4;   // [(kk*8+iq)*33 + o]

    // Tpart reduction (t<256) — issues immediately, overlaps other loads
    if (t < 256) {
        int kk0 = t >> 6, p = (t >> 5) & 1, o0 = t & 31;
        int k = kq * 4 + kk0;
        float a0 = 0.f;
#pragma unroll
        for (int Bg2 = 0; Bg2 < 8; Bg2++)
            a0 += g_Tpart[(((Bg2 * 2 + p) * 32 + s2) * 16 + k) * 32 + o0];
        tsh[t] = a0 * (1.f / 256.f);
    }
    // wdT slice -> smem, interleaved layout for single-phase LDS.128
#pragma unroll
    for (int j = 0; j < 2; j++) {
        int e = j * 512 + t;                           // e = kk*256 + o*8 + iq
        int kk2 = e >> 8, o2 = (e >> 3) & 31, iq2 = e & 7;
        wdsh4[(kk2 * 8 + iq2) * 33 + o2] = g_wdT4[(kq * 4 + kk2) * 256 + (e & 255)];
    }
    // xp row into registers (permS prefetched at kernel start)
    const int kk = t >> 7, a = (t >> 3) & 15, og = t & 7;
    const int n = permS[kk * 16 + a];
    float4 xr[8];
    {
        const float4* xrow = (const float4*)(x + s2 * XS + n * 32);
#pragma unroll
        for (int iq = 0; iq < 8; iq++) xr[iq] = __ldg(&xrow[iq]);
    }
    __syncthreads();

    const int pa = a >> 3;
    float acc2[4];
#pragma unroll
    for (int oo = 0; oo < 4; oo++)
        acc2[oo] = tsh[kk * 64 + pa * 32 + og + 8 * oo] + bsh[og + 8 * oo];
#pragma unroll
    for (int iq = 0; iq < 8; iq++) {
        float4 xv = xr[iq];
#pragma unroll
        for (int oo = 0; oo < 4; oo++) {
            float4 wv = wdsh4[(kk * 8 + iq) * 33 + og + 8 * oo];
            acc2[oo] += wv.x * xv.x + wv.y * xv.y + wv.z * xv.z + wv.w * xv.w;
        }
    }
    float* orow = out + s2 * XS + n * 32;
#pragma unroll
    for (int oo = 0; oo < 4; oo++) orow[og + 8 * oo] = acc2[oo];
}

// ---------------------------------------------------------------------------
extern "C" void kernel_launch(void* const* d_in, const int* in_sizes, int n_in,
                              void* d_out, int out_size)
{
    const float* x      = (const float*)d_in[0];
    const float* w_diag = (const float*)d_in[1];
    const float* w_off  = (const float*)d_in[2];
    const float* b1     = (const float*)d_in[3];
    const int*   perm   = (const int*)d_in[4];
    float* out = (float*)d_out;

    fused_kernel<<<NBLK, 512>>>(x, w_diag, w_off, b1, perm, out);
}

// round 6
// speedup vs baseline: 1.1779x; 1.1779x over previous
#include <cuda_runtime.h>

#define XS   8192
#define NBLK 128

// Scratch (allocation-free)
__device__ float4 g_Sp4[32 * 16 * 8];                 // [s][m^][iq]  (S[2m]+S[2m+1])
__device__ float4 g_Sm4[32 * 16 * 8];                 // [s][m^][iq]  (S[2m]-S[2m+1])
__device__ float4 g_wdT4[16 * 256];                   // [k][o*8+iq]
__device__ float  g_Tpart[8 * 2 * 32 * 16 * 32];      // [Bg][pq][s][k][o]
__device__ unsigned int g_cnt1[8];                    // per m-pair group (=Bg)
__device__ unsigned int g_cnt2[4];                    // per k-quad

__device__ __forceinline__ unsigned int ld_acq(const unsigned int* p) {
    unsigned int v;
    asm volatile("ld.acquire.gpu.u32 %0, [%1];" : "=r"(v) : "l"(p));
    return v;
}

__device__ __forceinline__ float4 shfl_xor_f4(float4 v, int d) {
    float4 r;
    r.x = __shfl_xor_sync(0xffffffffu, v.x, d);
    r.y = __shfl_xor_sync(0xffffffffu, v.y, d);
    r.z = __shfl_xor_sync(0xffffffffu, v.z, d);
    r.w = __shfl_xor_sync(0xffffffffu, v.w, d);
    return r;
}

__global__ void __launch_bounds__(512, 1) fused_kernel(
    const float* __restrict__ x,
    const float* __restrict__ w_diag,
    const float* __restrict__ w_off,
    const float* __restrict__ b1,
    const int*   __restrict__ perm,
    float*       __restrict__ out)
{
    // f4 layout: Wp [0,544), Wm [544,1088), Sp [1088,1632), Sm [1632,2176)
    // reused: stage floats [0,8448); phase2 wdsh4 [0,1056)
    __shared__ float4 SM4[2176];
    __shared__ float  tsh[256];
    __shared__ float  bsh[32];
    float* SMf = (float*)SM4;

    const int b = blockIdx.x, t = threadIdx.x;
    const int k1 = b >> 3, Bg = b & 7;        // phase-1 role
    const int s2 = b >> 2, kq = b & 3;        // phase-2 role

    if (t < 32) bsh[t] = __ldg(&b1[t]);

    // phase-2 indices + perm (early, off critical path)
    const int kk  = t >> 7;
    const int aa  = (t >> 3) & 15;
    const int og2 = t & 7;
    const int n2  = __ldg(&perm[kq * 64 + kk * 16 + aa]);

    // ---- W prefetch for phase 1 ----
    const float4* woff4 = (const float4*)w_off;     // [c][k][B/4]
    float4 wreg[2];
#pragma unroll
    for (int j = 0; j < 2; j++) {
        int c = j * 512 + t;                         // c = o*32+i
        wreg[j] = __ldg(&woff4[c * 128 + k1 * 8 + Bg]);
    }

    // ================= phase 0: S± pooling (block handles m^ = b>>3) ========
    {
        const int item = t >> 4, r = t & 15;
        const int mh = b >> 3;                       // m^ in 0..15
        const int sL = (b & 7) * 4 + (item >> 3);
        const int iq = item & 7;
        const int n = __ldg(&perm[mh * 16 + r]);
        const float4* x4 = (const float4*)x;
        float4 v = __ldg(&x4[sL * 2048 + n * 8 + iq]);
        v = shfl_xor_f4(v, 1); // accumulate within 8-lane halves
        // note: shfl_xor_f4 returns partner; do explicit adds:
        // (rewritten below properly)
        (void)v;
        // proper butterfly:
        float4 a = __ldg(&x4[sL * 2048 + n * 8 + iq]);
#pragma unroll
        for (int d = 1; d < 8; d <<= 1) {
            float4 o4 = shfl_xor_f4(a, d);
            a.x += o4.x; a.y += o4.y; a.z += o4.z; a.w += o4.w;
        }
        // lanes r<8 hold u (sum over B=2m^), lanes r>=8 hold v (B=2m^+1)
        float4 o4 = shfl_xor_f4(a, 8);
        if (r == 0) {
            float4 p, q;
            p.x = a.x + o4.x; p.y = a.y + o4.y; p.z = a.z + o4.z; p.w = a.w + o4.w;
            q.x = a.x - o4.x; q.y = a.y - o4.y; q.z = a.z - o4.z; q.w = a.w - o4.w;
            g_Sp4[(sL * 16 + mh) * 8 + iq] = p;
            g_Sm4[(sL * 16 + mh) * 8 + iq] = q;
        }
    }

    // ---- w_diag transpose (Bg==0 blocks), covered by cnt2 fence ----
    if (Bg == 0) {
        float* gw = (float*)g_wdT4;
#pragma unroll
        for (int j = 0; j < 2; j++) {
            int c = j * 512 + t;
            gw[k1 * 1024 + c] = __ldg(&w_diag[c * 16 + k1]);
        }
    }

    // ---- W± into smem (pre-wait) ----
    {
        float* Wp = SMf;
        float* Wm = SMf + 2176;
#pragma unroll
        for (int j = 0; j < 2; j++) {
            int c = j * 512 + t, o = c >> 5, i = c & 31;
            float4 w = wreg[j];
            Wp[o * 68 +      i] = w.x + w.y;
            Wm[o * 68 +      i] = w.x - w.y;
            Wp[o * 68 + 32 + i] = w.z + w.w;
            Wm[o * 68 + 32 + i] = w.z - w.w;
        }
    }

    // ---- sync 1: wait for the 16 producers of m-pair Bg ----
    __threadfence();
    __syncthreads();
    if (t == 0) {
        unsigned int my = atomicAdd(&g_cnt1[b >> 4], 1u);
        unsigned int tgt = ((my >> 4) + 1u) << 4;
        while (ld_acq(&g_cnt1[Bg]) < tgt) {}
    }
    __syncthreads();

    // ================= phase 1: P/Q partials =================
    {
        // S± slices -> smem
        int iq = t & 7, ml = (t >> 3) & 1, s = t >> 4;
        SM4[1088 + s * 17 + ml * 8 + iq] = __ldcg(&g_Sp4[(s * 16 + 2 * Bg + ml) * 8 + iq]);
        SM4[1632 + s * 17 + ml * 8 + iq] = __ldcg(&g_Sm4[(s * 16 + 2 * Bg + ml) * 8 + iq]);
    }
    __syncthreads();

    float accv[8][4];
    if (t < 256) {
        const int sq = t >> 6, pq = (t >> 5) & 1, og = (t >> 2) & 7, ih = t & 3;
        const float4* Wv = SM4 + (pq ? 544 : 0);
        const float4* Sv = SM4 + 1088 + (pq ? 544 : 0);
#pragma unroll
        for (int j = 0; j < 32; j++) ((float*)accv)[j] = 0.f;
#pragma unroll
        for (int m = 0; m < 2; m++)
#pragma unroll
            for (int c2 = 0; c2 < 2; c2++) {
                int ch = ih * 2 + c2;
                float4 sv[8];
#pragma unroll
                for (int ss = 0; ss < 8; ss++)
                    sv[ss] = Sv[(sq * 8 + ss) * 17 + m * 8 + ch];
#pragma unroll
                for (int oo = 0; oo < 4; oo++) {
                    float4 w = Wv[(og + 8 * oo) * 17 + m * 8 + ch];
#pragma unroll
                    for (int ss = 0; ss < 8; ss++)
                        accv[ss][oo] += w.x * sv[ss].x + w.y * sv[ss].y
                                      + w.z * sv[ss].z + w.w * sv[ss].w;
                }
            }
    }
    __syncthreads();
    if (t < 256) {
#pragma unroll
        for (int ss = 0; ss < 8; ss++)
#pragma unroll
            for (int oo = 0; oo < 4; oo++)
                SMf[t * 33 + ss * 4 + oo] = accv[ss][oo];
    }
    __syncthreads();
    if (t < 256) {   // reduce over ih (4 threads), write Tpart
        int g = t >> 2;
        int sq = t >> 6, pq = (t >> 5) & 1, og = (t >> 2) & 7;
#pragma unroll
        for (int jj = 0; jj < 8; jj++) {
            int j = (t & 3) * 8 + jj;
            float v = SMf[(g * 4 + 0) * 33 + j] + SMf[(g * 4 + 1) * 33 + j]
                    + SMf[(g * 4 + 2) * 33 + j] + SMf[(g * 4 + 3) * 33 + j];
            int ss = j >> 2, oo = j & 3;
            g_Tpart[(((Bg * 2 + pq) * 32 + (sq * 8 + ss)) * 16 + k1) * 32
                    + (og + 8 * oo)] = v;
        }
    }

    // ---- sync 2: wait for 32 producers of k-quad kq; pre-issue x gathers ----
    __threadfence();
    __syncthreads();
    unsigned int tgt2 = 0;
    if (t == 0) {
        unsigned int my = atomicAdd(&g_cnt2[b >> 5], 1u);
        tgt2 = ((my >> 5) + 1u) << 5;
    }
    float4 xr[8];
    {
        const float4* xrow = (const float4*)(x + s2 * XS + n2 * 32);
#pragma unroll
        for (int iq = 0; iq < 8; iq++) xr[iq] = __ldg(&xrow[iq]);
    }
    if (t == 0) { while (ld_acq(&g_cnt2[kq]) < tgt2) {} }
    __syncthreads();

    // ================= phase 2: finalize =================
    float4* wdsh4 = SM4;   // [(kk*8+iq)*33 + o]
#pragma unroll
    for (int j = 0; j < 2; j++) {
        int e = j * 512 + t;
        int kkk = e >> 8, o2 = (e >> 3) & 31, iqq = e & 7;
        wdsh4[(kkk * 8 + iqq) * 33 + o2] = __ldcg(&g_wdT4[(kq * 4 + kkk) * 256 + (e & 255)]);
    }
    if (t < 256) {
        int kk0 = t >> 6, p = (t >> 5) & 1, o0 = t & 31;
        int k = kq * 4 + kk0;
        float P = 0.f, Q = 0.f;
#pragma unroll
        for (int Bg2 = 0; Bg2 < 8; Bg2++) {
            P += __ldcg(&g_Tpart[(((Bg2 * 2 + 0) * 32 + s2) * 16 + k) * 32 + o0]);
            Q += __ldcg(&g_Tpart[(((Bg2 * 2 + 1) * 32 + s2) * 16 + k) * 32 + o0]);
        }
        tsh[t] = (p ? (P - Q) : (P + Q)) * (1.0f / 512.0f);
    }
    __syncthreads();

    const int pa = aa >> 3;
    float acc2[4];
#pragma unroll
    for (int oo = 0; oo < 4; oo++)
        acc2[oo] = tsh[kk * 64 + pa * 32 + og2 + 8 * oo] + bsh[og2 + 8 * oo];
#pragma unroll
    for (int iq = 0; iq < 8; iq++) {
        float4 xv = xr[iq];
#pragma unroll
        for (int oo = 0; oo < 4; oo++) {
            float4 wv = wdsh4[(kk * 8 + iq) * 33 + og2 + 8 * oo];
            acc2[oo] += wv.x * xv.x + wv.y * xv.y + wv.z * xv.z + wv.w * xv.w;
        }
    }
    float* orow = out + s2 * XS + n2 * 32;
#pragma unroll
    for (int oo = 0; oo < 4; oo++) orow[og2 + 8 * oo] = acc2[oo];
}

// ---------------------------------------------------------------------------
extern "C" void kernel_launch(void* const* d_in, const int* in_sizes, int n_in,
                              void* d_out, int out_size)
{
    const float* x      = (const float*)d_in[0];
    const float* w_diag = (const float*)d_in[1];
    const float* w_off  = (const float*)d_in[2];
    const float* b1     = (const float*)d_in[3];
    const int*   perm   = (const int*)d_in[4];
    float* out = (float*)d_out;

    fused_kernel<<<NBLK, 512>>>(x, w_diag, w_off, b1, perm, out);
}